// round 14
// baseline (speedup 1.0000x reference)
#include <cuda_runtime.h>
#include <cuda_fp16.h>
#include <cstdint>

// ---------------------------------------------------------------------------
// AtomAttentionEncoder fused pipeline (round 11: A-resident multi-B GEMM)
// B=2, N=16384, CA=CS=128, CZ=16, H=4, NQ=32, NK=128, DH=32, NB=512
// ---------------------------------------------------------------------------

constexpr int B_  = 2;
constexpr int N_  = 16384;
constexpr int CA_ = 128;
constexpr int CZ_ = 16;
constexpr int H_  = 4;
constexpr int NB_ = 512;

constexpr int    M_   = B_ * N_;               // 32768 tokens
constexpr size_t SLOT = (size_t)M_ * CA_;      // 4,194,304 floats

__device__ float g_scratch[13 * SLOT];

__device__ __forceinline__ float sigmoidf_(float x) { return 1.0f / (1.0f + __expf(-x)); }

#define MMA_F16(cc, aa, bb)                                                    \
    asm volatile("mma.sync.aligned.m16n8k16.row.col.f32.f16.f16.f32 "          \
                 "{%0,%1,%2,%3}, {%4,%5,%6,%7}, {%8,%9}, {%0,%1,%2,%3};"       \
                 : "+f"(cc[0]), "+f"(cc[1]), "+f"(cc[2]), "+f"(cc[3])          \
                 : "r"(aa[0]), "r"(aa[1]), "r"(aa[2]), "r"(aa[3]),             \
                   "r"(bb[0]), "r"(bb[1]))

__device__ __forceinline__ void cp_async16(uint32_t smem_addr, const void* gptr) {
    asm volatile("cp.async.cg.shared.global [%0], [%1], 16;\n"
                 :: "r"(smem_addr), "l"(gptr));
}
__device__ __forceinline__ void cp_commit() { asm volatile("cp.async.commit_group;\n"); }
__device__ __forceinline__ void cp_wait1()  { asm volatile("cp.async.wait_group 1;\n"); }
__device__ __forceinline__ void cp_wait0()  { asm volatile("cp.async.wait_group 0;\n"); }

__device__ __forceinline__ uint32_t smem_u32(const void* p) {
    uint32_t a;
    asm("{ .reg .u64 t; cvta.to.shared.u64 t, %1; cvt.u32.u64 %0, t; }" : "=r"(a) : "l"(p));
    return a;
}
__device__ __forceinline__ void ldsm_x4(uint32_t (&r)[4], uint32_t addr) {
    asm volatile("ldmatrix.sync.aligned.m8n8.x4.shared.b16 {%0,%1,%2,%3}, [%4];"
                 : "=r"(r[0]), "=r"(r[1]), "=r"(r[2]), "=r"(r[3]) : "r"(addr));
}
__device__ __forceinline__ void ldsm_x2(uint32_t (&r)[2], uint32_t addr) {
    asm volatile("ldmatrix.sync.aligned.m8n8.x2.shared.b16 {%0,%1}, [%2];"
                 : "=r"(r[0]), "=r"(r[1]) : "r"(addr));
}

// ---------------------------------------------------------------------------
// Weight conversion: Wt[n*K + k] = half(W[k*N + n])
// ---------------------------------------------------------------------------
struct WtPack {
    const float* src[14];
    __half*      dst[14];
    int          K[14];
    int          N[14];
};
__global__ void cvtw_kernel(WtPack p)
{
    int y = blockIdx.y;
    int K = p.K[y], N = p.N[y];
    const float* s = p.src[y];
    __half* d = p.dst[y];
    int total = K * N;
    for (int i = blockIdx.x * 256 + threadIdx.x; i < total; i += gridDim.x * 256) {
        int k = i / N, n = i % N;
        d[n * K + k] = __float2half(s[i]);
    }
}

// ---------------------------------------------------------------------------
// LayerNorm
// ---------------------------------------------------------------------------
__global__ void ln_kernel(const float* __restrict__ a, const float* __restrict__ s,
                          const float* __restrict__ apbg, const float* __restrict__ ctg,
                          float* __restrict__ a_n, __half* __restrict__ s_apbh,
                          __half* __restrict__ s_cth, __half* __restrict__ s_rh)
{
    int warp = (blockIdx.x * blockDim.x + threadIdx.x) >> 5;
    int lane = threadIdx.x & 31;
    if (warp >= M_) return;
    size_t base = (size_t)warp * CA_;

    float4 av = ((const float4*)(a + base))[lane];
    float sum = av.x + av.y + av.z + av.w;
    float sq  = av.x * av.x + av.y * av.y + av.z * av.z + av.w * av.w;
#pragma unroll
    for (int o = 16; o; o >>= 1) {
        sum += __shfl_xor_sync(0xffffffffu, sum, o);
        sq  += __shfl_xor_sync(0xffffffffu, sq,  o);
    }
    float m   = sum * (1.0f / 128.0f);
    float inv = rsqrtf(sq * (1.0f / 128.0f) - m * m + 1e-5f);
    float4 ao;
    ao.x = (av.x - m) * inv; ao.y = (av.y - m) * inv;
    ao.z = (av.z - m) * inv; ao.w = (av.w - m) * inv;
    ((float4*)(a_n + base))[lane] = ao;

    float4 sv = ((const float4*)(s + base))[lane];
    {
        __half* p = s_rh + base + lane * 4;
        *(__half2*)(p)     = __floats2half2_rn(sv.x, sv.y);
        *(__half2*)(p + 2) = __floats2half2_rn(sv.z, sv.w);
    }

    float sums = sv.x + sv.y + sv.z + sv.w;
    float sqs  = sv.x * sv.x + sv.y * sv.y + sv.z * sv.z + sv.w * sv.w;
#pragma unroll
    for (int o = 16; o; o >>= 1) {
        sums += __shfl_xor_sync(0xffffffffu, sums, o);
        sqs  += __shfl_xor_sync(0xffffffffu, sqs,  o);
    }
    float ms   = sums * (1.0f / 128.0f);
    float invs = rsqrtf(sqs * (1.0f / 128.0f) - ms * ms + 1e-5f);
    float4 sn;
    sn.x = (sv.x - ms) * invs; sn.y = (sv.y - ms) * invs;
    sn.z = (sv.z - ms) * invs; sn.w = (sv.w - ms) * invs;

    float4 g1 = ((const float4*)apbg)[lane];
    float4 g2 = ((const float4*)ctg)[lane];
    {
        __half* p = s_apbh + base + lane * 4;
        *(__half2*)(p)     = __floats2half2_rn(sn.x * g1.x, sn.y * g1.y);
        *(__half2*)(p + 2) = __floats2half2_rn(sn.z * g1.z, sn.w * g1.w);
    }
    {
        __half* p = s_cth + base + lane * 4;
        *(__half2*)(p)     = __floats2half2_rn(sn.x * g2.x, sn.y * g2.y);
        *(__half2*)(p + 2) = __floats2half2_rn(sn.z * g2.z, sn.w * g2.w);
    }
}

// ---------------------------------------------------------------------------
// Shared epilogue helper
// ---------------------------------------------------------------------------
struct EpiDesc {
    const float*  bias;
    void*         C;
    const __half* e1h;
    const float*  e2;
    int           ldC;
    int           ep;     // 0 none, 1 sigmoid, 2 e1h*acc, 3 e1h*acc+e2
    int           outh;   // 1 = write half
};

__device__ __forceinline__ void do_epilogue(
    float (&c)[4][4][4], const EpiDesc& d,
    int row0, int wm, int wn, int gid, int qid)
{
#pragma unroll
    for (int mi = 0; mi < 4; mi++) {
#pragma unroll
        for (int ni = 0; ni < 4; ni++) {
            int rA = row0 + wm + mi * 16 + gid;
            int cc = wn + ni * 8 + qid * 2;
            float b0 = d.bias ? d.bias[cc]     : 0.0f;
            float b1 = d.bias ? d.bias[cc + 1] : 0.0f;
#pragma unroll
            for (int h = 0; h < 2; h++) {
                size_t idx = (size_t)(rA + h * 8) * d.ldC + cc;
                float v0 = c[mi][ni][h * 2 + 0] + b0;
                float v1 = c[mi][ni][h * 2 + 1] + b1;
                if (d.ep == 1)      { v0 = sigmoidf_(v0); v1 = sigmoidf_(v1); }
                else if (d.ep == 2) {
                    __half2 e = *(const __half2*)(d.e1h + idx);
                    v0 *= __low2float(e); v1 *= __high2float(e);
                } else if (d.ep == 3) {
                    __half2 e = *(const __half2*)(d.e1h + idx);
                    v0 = __low2float(e)  * v0 + d.e2[idx];
                    v1 = __high2float(e) * v1 + d.e2[idx + 1];
                }
                if (d.outh) *(__half2*)((__half*)d.C + idx) = __floats2half2_rn(v0, v1);
                else        *(float2*)((float*)d.C + idx)   = make_float2(v0, v1);
            }
        }
    }
}

// ---------------------------------------------------------------------------
// A-resident multi-B GEMM (K=128 only).
// CTA: 128 rows; loads A once; iterates nseg weight matrices with
// double-buffered cp.async B prefetch. grid.y = group.
// ---------------------------------------------------------------------------
struct ArSeg { const __half* Wt; EpiDesc epi; };
struct ArGroup { const __half* A; int nseg; ArSeg seg[4]; };
struct ArArgs { ArGroup grp[3]; };

constexpr int ARSZ = 128 * 136;                       // halves per tile
constexpr int AR_SMEM = 3 * ARSZ * 2;                 // A + 2 B buffers = 104448 B

__global__ void __launch_bounds__(256, 2) gemm_ar(ArArgs args)
{
    extern __shared__ __half smh[];
    int tid  = threadIdx.x;
    int warp = tid >> 5, lane = tid & 31;
    int wm = (warp >> 2) * 64;
    int wn = (warp & 3) * 32;
    int gid = lane >> 2, qid = lane & 3;
    int row0 = blockIdx.x * 128;
    const ArGroup& grp = args.grp[blockIdx.y];
    const __half* A = grp.A;
    int nseg = grp.nseg;

    uint32_t smBase = smem_u32(smh);
    int lmA = lane & 15, lhA = (lane >> 4) << 3;
    int lmB = lane & 7,  lhB = ((lane >> 3) & 1) << 3;

    // issue A tile (128x128) into smem slab 0
#pragma unroll
    for (int i = 0; i < 8; i++) {
        int e  = tid + i * 256;
        int r  = e >> 4;
        int c8 = (e & 15) * 8;
        uint32_t dst = smBase + (uint32_t)(r * 136 + c8) * 2u;
        cp_async16(dst, A + (size_t)(row0 + r) * 128 + c8);
    }
    // issue B0 into buffer 0
    auto issueB = [&](int sidx, int buf) {
        const __half* Wt = grp.seg[sidx].Wt;
#pragma unroll
        for (int i = 0; i < 8; i++) {
            int e  = tid + i * 256;
            int n  = e >> 4;
            int c8 = (e & 15) * 8;
            uint32_t dst = smBase + (uint32_t)((1 + buf) * ARSZ + n * 136 + c8) * 2u;
            cp_async16(dst, Wt + (size_t)n * 128 + c8);
        }
    };
    issueB(0, 0); cp_commit();
    if (nseg > 1) { issueB(1, 1); cp_commit(); }

    for (int sidx = 0; sidx < nseg; sidx++) {
        if (sidx + 1 < nseg) cp_wait1(); else cp_wait0();
        __syncthreads();

        uint32_t asB = smBase;
        uint32_t bsB = smBase + (uint32_t)((1 + (sidx & 1)) * ARSZ) * 2u;

        float c[4][4][4];
#pragma unroll
        for (int mi = 0; mi < 4; mi++)
#pragma unroll
            for (int ni = 0; ni < 4; ni++)
#pragma unroll
                for (int r = 0; r < 4; r++) c[mi][ni][r] = 0.0f;

#pragma unroll
        for (int ks = 0; ks < 8; ks++) {
            int kb = ks * 16;
            uint32_t af[4][4], bf[4][2];
#pragma unroll
            for (int mi = 0; mi < 4; mi++)
                ldsm_x4(af[mi], asB + (uint32_t)((wm + mi * 16 + lmA) * 136 + kb + lhA) * 2u);
#pragma unroll
            for (int ni = 0; ni < 4; ni++)
                ldsm_x2(bf[ni], bsB + (uint32_t)((wn + ni * 8 + lmB) * 136 + kb + lhB) * 2u);
#pragma unroll
            for (int mi = 0; mi < 4; mi++)
#pragma unroll
                for (int ni = 0; ni < 4; ni++)
                    MMA_F16(c[mi][ni], af[mi], bf[ni]);
        }
        __syncthreads();   // all warps done reading this B buffer

        if (sidx + 2 < nseg) { issueB(sidx + 2, sidx & 1); cp_commit(); }

        do_epilogue(c, grp.seg[sidx].epi, row0, wm, wn, gid, qid);
    }
}

// ---------------------------------------------------------------------------
// K=256 GEMM with fused silu loader (G3 only): old-style double-buffer on K.
// ---------------------------------------------------------------------------
constexpr int HST = 128 * 72;                 // halves per stage
constexpr int GEMM_SMEM = 4 * HST * 2;        // 73728 bytes

__global__ void __launch_bounds__(256, 2) gemm_h(
    const __half* __restrict__ U1h, const __half* __restrict__ U2h,
    const __half* __restrict__ Wt, EpiDesc epi)
{
    extern __shared__ __half smh[];
    const int K = 256;
    int tid  = threadIdx.x;
    int warp = tid >> 5, lane = tid & 31;
    int wm = (warp >> 2) * 64;
    int wn = (warp & 3) * 32;
    int gid = lane >> 2, qid = lane & 3;
    int row0 = blockIdx.x * 128;
    int KT = K >> 6;  // 4

    uint32_t smBase = smem_u32(smh);
    int lmA = lane & 15, lhA = (lane >> 4) << 3;
    int lmB = lane & 7,  lhB = ((lane >> 3) & 1) << 3;

    auto loadA = [&](int kt, int st) {
        __half* As = smh + st * HST;
#pragma unroll
        for (int i = 0; i < 4; i++) {
            int e  = tid + i * 256;
            int r  = e >> 3;
            int c8 = (e & 7) * 8;
            size_t off = (size_t)(row0 + r) * K + kt * 64 + c8;
            uint4 xu = *(const uint4*)(U1h + off);
            uint4 wu = *(const uint4*)(U2h + off);
            const __half2* xh = (const __half2*)&xu;
            const __half2* wh2 = (const __half2*)&wu;
            __half2 outp[4];
#pragma unroll
            for (int j = 0; j < 4; j++) {
                float2 xf = __half22float2(xh[j]);
                float2 wf = __half22float2(wh2[j]);
                outp[j] = __floats2half2_rn(xf.x * sigmoidf_(xf.x) * wf.x,
                                            xf.y * sigmoidf_(xf.y) * wf.y);
            }
            *(uint4*)(As + r * 72 + c8) = *(uint4*)outp;
        }
    };
    auto loadB = [&](int kt, int st) {
#pragma unroll
        for (int i = 0; i < 4; i++) {
            int e  = tid + i * 256;
            int n  = e >> 3;
            int c8 = (e & 7) * 8;
            uint32_t dst = smBase + (uint32_t)(2 * HST + st * HST + n * 72 + c8) * 2u;
            cp_async16(dst, Wt + (size_t)n * K + kt * 64 + c8);
        }
    };

    float c[4][4][4];
#pragma unroll
    for (int mi = 0; mi < 4; mi++)
#pragma unroll
        for (int ni = 0; ni < 4; ni++)
#pragma unroll
            for (int r = 0; r < 4; r++) c[mi][ni][r] = 0.0f;

    loadA(0, 0); loadB(0, 0); cp_commit();
    loadA(1, 1); loadB(1, 1); cp_commit();

    for (int kt = 0; kt < KT; kt++) {
        cp_wait1();
        __syncthreads();
        int st = kt & 1;
        uint32_t asB = smBase + (uint32_t)(st * HST) * 2u;
        uint32_t bsB = smBase + (uint32_t)(2 * HST + st * HST) * 2u;
#pragma unroll
        for (int ks = 0; ks < 4; ks++) {
            int kb = ks * 16;
            uint32_t af[4][4], bf[4][2];
#pragma unroll
            for (int mi = 0; mi < 4; mi++)
                ldsm_x4(af[mi], asB + (uint32_t)((wm + mi * 16 + lmA) * 72 + kb + lhA) * 2u);
#pragma unroll
            for (int ni = 0; ni < 4; ni++)
                ldsm_x2(bf[ni], bsB + (uint32_t)((wn + ni * 8 + lmB) * 72 + kb + lhB) * 2u);
#pragma unroll
            for (int mi = 0; mi < 4; mi++)
#pragma unroll
                for (int ni = 0; ni < 4; ni++)
                    MMA_F16(c[mi][ni], af[mi], bf[ni]);
        }
        __syncthreads();
        if (kt + 2 < KT) { loadA(kt + 2, st); loadB(kt + 2, st); }
        cp_commit();
    }

    do_epilogue(c, epi, row0, wm, wn, gid, qid);
}

// ---------------------------------------------------------------------------
// Combine: a1h = h(gapb*a_n + kapb); a3h = h(gct*a_n + kct)
// ---------------------------------------------------------------------------
__global__ void combine1_kernel(
    const __half* __restrict__ gapbh, const __half* __restrict__ kapbh,
    const __half* __restrict__ gcth,  const __half* __restrict__ kcth,
    const float* __restrict__ a_n,
    __half* __restrict__ a1h, __half* __restrict__ a3h)
{
    size_t i = (size_t)blockIdx.x * blockDim.x + threadIdx.x;
    float4 van = ((const float4*)a_n)[i];

    {
        __half2 g0 = ((const __half2*)gapbh)[2 * i], g1 = ((const __half2*)gapbh)[2 * i + 1];
        __half2 k0 = ((const __half2*)kapbh)[2 * i], k1 = ((const __half2*)kapbh)[2 * i + 1];
        float2 gf0 = __half22float2(g0), gf1 = __half22float2(g1);
        float2 kf0 = __half22float2(k0), kf1 = __half22float2(k1);
        ((__half2*)a1h)[2 * i]     = __floats2half2_rn(gf0.x * van.x + kf0.x, gf0.y * van.y + kf0.y);
        ((__half2*)a1h)[2 * i + 1] = __floats2half2_rn(gf1.x * van.z + kf1.x, gf1.y * van.w + kf1.y);
    }
    {
        __half2 g0 = ((const __half2*)gcth)[2 * i], g1 = ((const __half2*)gcth)[2 * i + 1];
        __half2 k0 = ((const __half2*)kcth)[2 * i], k1 = ((const __half2*)kcth)[2 * i + 1];
        float2 gf0 = __half22float2(g0), gf1 = __half22float2(g1);
        float2 kf0 = __half22float2(k0), kf1 = __half22float2(k1);
        ((__half2*)a3h)[2 * i]     = __floats2half2_rn(gf0.x * van.x + kf0.x, gf0.y * van.y + kf0.y);
        ((__half2*)a3h)[2 * i + 1] = __floats2half2_rn(gf1.x * van.z + kf1.x, gf1.y * van.w + kf1.y);
    }
}

// ---------------------------------------------------------------------------
// Tensor-core local attention (unchanged from round 9).
// ---------------------------------------------------------------------------
constexpr int ATTN_SMEM_BYTES = (4 * 4224 + 4224) * 4 + (4352 + 17408 + 17408 + 4352) * 2;

__global__ void __launch_bounds__(256) attn_kernel(
    const __half* __restrict__ qh, const __half* __restrict__ kh,
    const __half* __restrict__ vh, const float* __restrict__ z,
    const float* __restrict__ gamma_z, const float* __restrict__ Wz,
    const __half* __restrict__ gh, __half* __restrict__ obh)
{
    extern __shared__ float sm[];
    float* biasS = sm;
    float* scp   = sm + 4 * 4224;
    __half* Qs = (__half*)(sm + 5 * 4224);
    __half* Ks = Qs + 4352;
    __half* Vs = Ks + 17408;
    __half* Ps = Vs + 17408;
    __shared__ float gzs[CZ_];
    __shared__ float wzs[CZ_ * H_];

    int tid = threadIdx.x;
    int warp = tid >> 5, lane = tid & 31;
    int gid = lane >> 2, qid = lane & 3;
    int nb = blockIdx.x, b = blockIdx.y;
    if (tid < CZ_)      gzs[tid] = gamma_z[tid];
    if (tid < CZ_ * H_) wzs[tid] = Wz[tid];

    int kbase = nb * 32 - 48;
    int lmA = lane & 15, lhA = (lane >> 4) << 3;
    int lmB = lane & 7,  lhB = ((lane >> 3) & 1) << 3;

    for (int e = tid; e < 512; e += 256) {
        int qq = e >> 4, c8 = (e & 15) * 8;
        *(float4*)(Qs + qq * 136 + c8) =
            *(const float4*)(qh + ((size_t)b * N_ + nb * 32 + qq) * 128 + c8);
    }
    for (int e = tid; e < 2048; e += 256) {
        int j = e >> 4, c8 = (e & 15) * 8;
        int t = kbase + j;
        t = t < 0 ? 0 : (t >= N_ ? N_ - 1 : t);
        size_t off = ((size_t)b * N_ + t) * 128 + c8;
        *(float4*)(Ks + j * 136 + c8) = *(const float4*)(kh + off);
        *(float4*)(Vs + j * 136 + c8) = *(const float4*)(vh + off);
    }
    __syncthreads();

    const float* zb = z + ((size_t)(b * NB_ + nb)) * 4096 * CZ_;
#pragma unroll 2
    for (int i = 0; i < 16; i++) {
        int p = tid + i * 256;
        const float4* zp = (const float4*)(zb + (size_t)p * CZ_);
        float4 z0 = zp[0], z1 = zp[1], z2 = zp[2], z3 = zp[3];
        float zv[16] = {z0.x, z0.y, z0.z, z0.w, z1.x, z1.y, z1.z, z1.w,
                        z2.x, z2.y, z2.z, z2.w, z3.x, z3.y, z3.z, z3.w};
        float mm = 0.0f;
#pragma unroll
        for (int c = 0; c < 16; c++) mm += zv[c];
        mm *= (1.0f / 16.0f);
        float ss2 = 0.0f;
#pragma unroll
        for (int c = 0; c < 16; c++) { float d = zv[c] - mm; ss2 += d * d; }
        float inv = rsqrtf(ss2 * (1.0f / 16.0f) + 1e-5f);
        float bh0 = 0, bh1 = 0, bh2 = 0, bh3 = 0;
#pragma unroll
        for (int c = 0; c < 16; c++) {
            float zn = (zv[c] - mm) * inv * gzs[c];
            bh0 += zn * wzs[c * 4 + 0];
            bh1 += zn * wzs[c * 4 + 1];
            bh2 += zn * wzs[c * 4 + 2];
            bh3 += zn * wzs[c * 4 + 3];
        }
        int qq = p >> 7, kk = p & 127;
        int o2 = qq * 132 + kk;
        biasS[0 * 4224 + o2] = bh0;
        biasS[1 * 4224 + o2] = bh1;
        biasS[2 * 4224 + o2] = bh2;
        biasS[3 * 4224 + o2] = bh3;
    }
    __syncthreads();

    uint32_t qsBase = smem_u32(Qs);
    uint32_t ksBase = smem_u32(Ks);
    uint32_t vsBase = smem_u32(Vs);
    uint32_t psBase = smem_u32(Ps);
    const float SCALE = 0.17677669529663687f;

    for (int h = 0; h < H_; h++) {
        {
            int m0 = (warp >> 2) * 16;
            int n0 = (warp & 3) * 32;
            float c[4][4];
#pragma unroll
            for (int nt = 0; nt < 4; nt++)
#pragma unroll
                for (int r = 0; r < 4; r++) c[nt][r] = 0.0f;
#pragma unroll
            for (int ks = 0; ks < 2; ks++) {
                int kb = ks * 16;
                uint32_t af[4];
                ldsm_x4(af, qsBase + (uint32_t)((m0 + lmA) * 136 + h * 32 + kb + lhA) * 2u);
#pragma unroll
                for (int nt = 0; nt < 4; nt++) {
                    uint32_t bf[2];
                    ldsm_x2(bf, ksBase + (uint32_t)((n0 + nt * 8 + lmB) * 136 + h * 32 + kb + lhB) * 2u);
                    MMA_F16(c[nt], af, bf);
                }
            }
#pragma unroll
            for (int nt = 0; nt < 4; nt++) {
                int col = n0 + nt * 8 + 2 * qid;
                int r0 = m0 + gid, r1 = r0 + 8;
                bool ok0 = (kbase + col >= 0) && (kbase + col < N_);
                bool ok1 = (kbase + col + 1 >= 0) && (kbase + col + 1 < N_);
                const float* bh = biasS + h * 4224;
                scp[r0 * 132 + col]     = ok0 ? c[nt][0] * SCALE + bh[r0 * 132 + col]     : -1e9f;
                scp[r0 * 132 + col + 1] = ok1 ? c[nt][1] * SCALE + bh[r0 * 132 + col + 1] : -1e9f;
                scp[r1 * 132 + col]     = ok0 ? c[nt][2] * SCALE + bh[r1 * 132 + col]     : -1e9f;
                scp[r1 * 132 + col + 1] = ok1 ? c[nt][3] * SCALE + bh[r1 * 132 + col + 1] : -1e9f;
            }
        }
        __syncthreads();

#pragma unroll
        for (int rr = 0; rr < 4; rr++) {
            int r = warp * 4 + rr;
            const float* row = scp + r * 132;
            float v0 = row[lane], v1 = row[lane + 32], v2 = row[lane + 64], v3 = row[lane + 96];
            float mx = fmaxf(fmaxf(v0, v1), fmaxf(v2, v3));
#pragma unroll
            for (int o2 = 16; o2; o2 >>= 1) mx = fmaxf(mx, __shfl_xor_sync(0xffffffffu, mx, o2));
            v0 = __expf(v0 - mx); v1 = __expf(v1 - mx);
            v2 = __expf(v2 - mx); v3 = __expf(v3 - mx);
            float sumv = v0 + v1 + v2 + v3;
#pragma unroll
            for (int o2 = 16; o2; o2 >>= 1) sumv += __shfl_xor_sync(0xffffffffu, sumv, o2);
            float invs = 1.0f / sumv;
            __half* pr = Ps + r * 136;
            pr[lane]      = __float2half(v0 * invs);
            pr[lane + 32] = __float2half(v1 * invs);
            pr[lane + 64] = __float2half(v2 * invs);
            pr[lane + 96] = __float2half(v3 * invs);
        }
        __syncthreads();

        {
            int m0 = (warp >> 2) * 16;
            int nd0 = (warp & 3) * 8;
            float o[4] = {0.0f, 0.0f, 0.0f, 0.0f};
#pragma unroll
            for (int kb = 0; kb < 8; kb++) {
                uint32_t af[4];
                ldsm_x4(af, psBase + (uint32_t)((m0 + lmA) * 136 + kb * 16 + lhA) * 2u);
                int l = lane & 15;
                uint32_t addr = vsBase + (uint32_t)((kb * 16 + l) * 136 + h * 32 + nd0) * 2u;
                uint32_t bf[2];
                asm volatile("ldmatrix.sync.aligned.m8n8.x2.trans.shared.b16 {%0,%1}, [%2];"
                             : "=r"(bf[0]), "=r"(bf[1]) : "r"(addr));
                MMA_F16(o, af, bf);
            }
            int r0 = m0 + gid;
            size_t t0 = ((size_t)b * N_ + nb * 32 + r0) * 128 + h * 32 + nd0 + 2 * qid;
            size_t t1 = t0 + (size_t)8 * 128;
            float2 g0 = __half22float2(*(const __half2*)(gh + t0));
            float2 g1 = __half22float2(*(const __half2*)(gh + t1));
            *(__half2*)(obh + t0) = __floats2half2_rn(g0.x * o[0], g0.y * o[1]);
            *(__half2*)(obh + t1) = __floats2half2_rn(g1.x * o[2], g1.y * o[3]);
        }
        __syncthreads();
    }
}

// ---------------------------------------------------------------------------
// Host launch
// ---------------------------------------------------------------------------
extern "C" void kernel_launch(void* const* d_in, const int* in_sizes, int n_in,
                              void* d_out, int out_size)
{
    const float* a       = (const float*)d_in[0];
    const float* s       = (const float*)d_in[1];
    const float* z       = (const float*)d_in[2];
    const float* apb_gam = (const float*)d_in[3];
    const float* apb_Wg  = (const float*)d_in[4];
    const float* apb_bg  = (const float*)d_in[5];
    const float* apb_Wsk = (const float*)d_in[6];
    const float* Wq      = (const float*)d_in[7];
    const float* bq      = (const float*)d_in[8];
    const float* Wk      = (const float*)d_in[9];
    const float* Wv      = (const float*)d_in[10];
    const float* Wgate   = (const float*)d_in[11];
    const float* Wo      = (const float*)d_in[12];
    const float* gamma_z = (const float*)d_in[13];
    const float* Wz      = (const float*)d_in[14];
    const float* Ws_last = (const float*)d_in[15];
    const float* bs_last = (const float*)d_in[16];
    const float* ct_gam  = (const float*)d_in[17];
    const float* ct_Wg   = (const float*)d_in[18];
    const float* ct_bg   = (const float*)d_in[19];
    const float* ct_Wsk  = (const float*)d_in[20];
    const float* Wa1     = (const float*)d_in[21];
    const float* Wa2     = (const float*)d_in[22];
    const float* Wb      = (const float*)d_in[23];
    const float* Ws      = (const float*)d_in[24];
    const float* bsv     = (const float*)d_in[25];
    float* out = (float*)d_out;

    float* S = nullptr;
    cudaGetSymbolAddress((void**)&S, g_scratch);
    float* a_n = S;
    float* ctp = S + SLOT;
    __half* HB = (__half*)(S + 2 * SLOT);
    auto hslot = [&](int k) { return HB + (size_t)k * SLOT; };
    __half* u1h    = hslot(0);   // M x 256
    __half* u2h    = hslot(2);   // M x 256
    __half* s_apbh = hslot(4);
    __half* s_cth  = hslot(5);
    __half* s_rh   = hslot(6);
    __half* a1h    = hslot(7);
    __half* a3h    = hslot(8);
    __half* obh    = hslot(9);
    __half* gapbh  = hslot(10);
    __half* kapbh  = hslot(11);
    __half* gcth   = hslot(12);
    __half* kcth   = hslot(13);
    __half* glasth = hslot(14);
    __half* sgh    = hslot(15);
    __half* qh     = hslot(16);
    __half* khb    = hslot(17);
    __half* vhb    = hslot(18);
    __half* ghb    = hslot(19);
    __half* wh     = hslot(20);  // weights

    __half* wWg   = wh + 0;
    __half* wWsk  = wh + 16384;
    __half* wcWg  = wh + 32768;
    __half* wcWsk = wh + 49152;
    __half* wWsl  = wh + 65536;
    __half* wWs   = wh + 81920;
    __half* wWq   = wh + 98304;
    __half* wWk   = wh + 114688;
    __half* wWv   = wh + 131072;
    __half* wWgt  = wh + 147456;
    __half* wWo   = wh + 163840;
    __half* wWa1  = wh + 180224;  // [256][128]
    __half* wWa2  = wh + 212992;
    __half* wWb   = wh + 245760;  // [128][256]

    WtPack wp;
    const float* wsrc[14] = {apb_Wg, apb_Wsk, ct_Wg, ct_Wsk, Ws_last, Ws, Wq, Wk, Wv,
                             Wgate, Wo, Wa1, Wa2, Wb};
    __half* wdst[14] = {wWg, wWsk, wcWg, wcWsk, wWsl, wWs, wWq, wWk, wWv,
                        wWgt, wWo, wWa1, wWa2, wWb};
    int wK[14] = {128,128,128,128,128,128,128,128,128,128,128,128,128,256};
    int wN[14] = {128,128,128,128,128,128,128,128,128,128,128,256,256,128};
    for (int i = 0; i < 14; i++) { wp.src[i] = wsrc[i]; wp.dst[i] = wdst[i];
                                   wp.K[i] = wK[i]; wp.N[i] = wN[i]; }
    cvtw_kernel<<<dim3(16, 14), 256>>>(wp);

    ln_kernel<<<M_ / 8, 256>>>(a, s, apb_gam, ct_gam, a_n, s_apbh, s_cth, s_rh);

    cudaFuncSetAttribute(gemm_ar, cudaFuncAttributeMaxDynamicSharedMemorySize, AR_SMEM);
    cudaFuncSetAttribute(gemm_h, cudaFuncAttributeMaxDynamicSharedMemorySize, GEMM_SMEM);
    cudaFuncSetAttribute(attn_kernel, cudaFuncAttributeMaxDynamicSharedMemorySize,
                         ATTN_SMEM_BYTES);

    auto mkepi = [&](const float* bias, void* C, int ep, const __half* e1h,
                     const float* e2, int ldC, int outh) {
        EpiDesc d; d.bias = bias; d.C = C; d.e1h = e1h; d.e2 = e2;
        d.ldC = ldC; d.ep = ep; d.outh = outh; return d;
    };

    // G1: 3 groups x 2 segments (A-resident)
    {
        ArArgs g{};
        g.grp[0].A = s_apbh; g.grp[0].nseg = 2;
        g.grp[0].seg[0] = {wWg,   mkepi(apb_bg,  gapbh,  1, nullptr, nullptr, 128, 1)};
        g.grp[0].seg[1] = {wWsk,  mkepi(nullptr, kapbh,  0, nullptr, nullptr, 128, 1)};
        g.grp[1].A = s_cth;  g.grp[1].nseg = 2;
        g.grp[1].seg[0] = {wcWg,  mkepi(ct_bg,   gcth,   1, nullptr, nullptr, 128, 1)};
        g.grp[1].seg[1] = {wcWsk, mkepi(nullptr, kcth,   0, nullptr, nullptr, 128, 1)};
        g.grp[2].A = s_rh;   g.grp[2].nseg = 2;
        g.grp[2].seg[0] = {wWsl,  mkepi(bs_last, glasth, 1, nullptr, nullptr, 128, 1)};
        g.grp[2].seg[1] = {wWs,   mkepi(bsv,     sgh,    1, nullptr, nullptr, 128, 1)};
        gemm_ar<<<dim3(M_ / 128, 3), 256, AR_SMEM>>>(g);
    }

    combine1_kernel<<<(int)(SLOT / 4 / 256), 256>>>(gapbh, kapbh, gcth, kcth, a_n, a1h, a3h);

    // G2: 2 groups x 4 segments (A-resident)
    {
        ArArgs g{};
        g.grp[0].A = a1h; g.grp[0].nseg = 4;
        g.grp[0].seg[0] = {wWq,  mkepi(bq,      qh,   0, nullptr, nullptr, 128, 1)};
        g.grp[0].seg[1] = {wWk,  mkepi(nullptr, khb,  0, nullptr, nullptr, 128, 1)};
        g.grp[0].seg[2] = {wWv,  mkepi(nullptr, vhb,  0, nullptr, nullptr, 128, 1)};
        g.grp[0].seg[3] = {wWgt, mkepi(nullptr, ghb,  1, nullptr, nullptr, 128, 1)};
        g.grp[1].A = a3h; g.grp[1].nseg = 4;
        g.grp[1].seg[0] = {wWa1,         mkepi(nullptr, u1h,       0, nullptr, nullptr, 256, 1)};
        g.grp[1].seg[1] = {wWa1 + 16384, mkepi(nullptr, u1h + 128, 0, nullptr, nullptr, 256, 1)};
        g.grp[1].seg[2] = {wWa2,         mkepi(nullptr, u2h,       0, nullptr, nullptr, 256, 1)};
        g.grp[1].seg[3] = {wWa2 + 16384, mkepi(nullptr, u2h + 128, 0, nullptr, nullptr, 256, 1)};
        gemm_ar<<<dim3(M_ / 128, 2), 256, AR_SMEM>>>(g);
    }

    // G3: ct_out = sgh * (silu(u1)*u2 @ Wb), K=256 (fused loader)
    gemm_h<<<dim3(M_ / 128, 1), 256, GEMM_SMEM>>>(
        u1h, u2h, wWb, mkepi(nullptr, ctp, 2, sgh, nullptr, 128, 0));

    // attention
    attn_kernel<<<dim3(NB_, B_), 256, ATTN_SMEM_BYTES>>>(
        qh, khb, vhb, z, gamma_z, Wz, ghb, obh);

    // G4: out = glasth * (obh @ Wo) + ctp  (A-resident, 1 segment)
    {
        ArArgs g{};
        g.grp[0].A = obh; g.grp[0].nseg = 1;
        g.grp[0].seg[0] = {wWo, mkepi(nullptr, out, 3, glasth, ctp, 128, 0)};
        gemm_ar<<<dim3(M_ / 128, 1), 256, AR_SMEM>>>(g);
    }
}

// round 17
// speedup vs baseline: 1.2420x; 1.2420x over previous
#include <cuda_runtime.h>
#include <cuda_fp16.h>
#include <cstdint>

// ---------------------------------------------------------------------------
// AtomAttentionEncoder fused pipeline (round 15: R10 GEMMs + split z-bias +
// 2-CTA/SM tensor-core attention)
// B=2, N=16384, CA=CS=128, CZ=16, H=4, NQ=32, NK=128, DH=32, NB=512
// ---------------------------------------------------------------------------

constexpr int B_  = 2;
constexpr int N_  = 16384;
constexpr int CA_ = 128;
constexpr int CZ_ = 16;
constexpr int H_  = 4;
constexpr int NB_ = 512;

constexpr int    M_   = B_ * N_;               // 32768 tokens
constexpr size_t SLOT = (size_t)M_ * CA_;      // 4,194,304 floats

__device__ float g_scratch[15 * SLOT];

__device__ __forceinline__ float sigmoidf_(float x) { return 1.0f / (1.0f + __expf(-x)); }

#define MMA_F16(cc, aa, bb)                                                    \
    asm volatile("mma.sync.aligned.m16n8k16.row.col.f32.f16.f16.f32 "          \
                 "{%0,%1,%2,%3}, {%4,%5,%6,%7}, {%8,%9}, {%0,%1,%2,%3};"       \
                 : "+f"(cc[0]), "+f"(cc[1]), "+f"(cc[2]), "+f"(cc[3])          \
                 : "r"(aa[0]), "r"(aa[1]), "r"(aa[2]), "r"(aa[3]),             \
                   "r"(bb[0]), "r"(bb[1]))

__device__ __forceinline__ void cp_async16(uint32_t smem_addr, const void* gptr) {
    asm volatile("cp.async.cg.shared.global [%0], [%1], 16;\n"
                 :: "r"(smem_addr), "l"(gptr));
}
__device__ __forceinline__ void cp_commit() { asm volatile("cp.async.commit_group;\n"); }
__device__ __forceinline__ void cp_wait1()  { asm volatile("cp.async.wait_group 1;\n"); }

__device__ __forceinline__ uint32_t smem_u32(const void* p) {
    uint32_t a;
    asm("{ .reg .u64 t; cvta.to.shared.u64 t, %1; cvt.u32.u64 %0, t; }" : "=r"(a) : "l"(p));
    return a;
}
__device__ __forceinline__ void ldsm_x4(uint32_t (&r)[4], uint32_t addr) {
    asm volatile("ldmatrix.sync.aligned.m8n8.x4.shared.b16 {%0,%1,%2,%3}, [%4];"
                 : "=r"(r[0]), "=r"(r[1]), "=r"(r[2]), "=r"(r[3]) : "r"(addr));
}
__device__ __forceinline__ void ldsm_x2(uint32_t (&r)[2], uint32_t addr) {
    asm volatile("ldmatrix.sync.aligned.m8n8.x2.shared.b16 {%0,%1}, [%2];"
                 : "=r"(r[0]), "=r"(r[1]) : "r"(addr));
}

// ---------------------------------------------------------------------------
// Weight conversion: Wt[n*K + k] = half(W[k*N + n])
// ---------------------------------------------------------------------------
struct WtPack {
    const float* src[14];
    __half*      dst[14];
    int          K[14];
    int          N[14];
};
__global__ void cvtw_kernel(WtPack p)
{
    int y = blockIdx.y;
    int K = p.K[y], N = p.N[y];
    const float* s = p.src[y];
    __half* d = p.dst[y];
    int total = K * N;
    for (int i = blockIdx.x * 256 + threadIdx.x; i < total; i += gridDim.x * 256) {
        int k = i / N, n = i % N;
        d[n * K + k] = __float2half(s[i]);
    }
}

// ---------------------------------------------------------------------------
// z-bias kernel: biasg[bnb][h][q*128+k] = half( (LN(z)*gamma_z) @ Wz )
// One thread per (bnb, pair). Full occupancy, pure streaming.
// ---------------------------------------------------------------------------
__global__ void __launch_bounds__(256) biasz_kernel(
    const float* __restrict__ z, const float* __restrict__ gamma_z,
    const float* __restrict__ Wz, __half* __restrict__ biasg)
{
    __shared__ float gzs[CZ_];
    __shared__ float wzs[CZ_ * H_];
    if (threadIdx.x < CZ_)      gzs[threadIdx.x] = gamma_z[threadIdx.x];
    if (threadIdx.x < CZ_ * H_) wzs[threadIdx.x] = Wz[threadIdx.x];
    __syncthreads();

    size_t p = (size_t)blockIdx.x * 256 + threadIdx.x;   // over B*NB*4096
    const float4* zp = (const float4*)(z + p * CZ_);
    float4 z0 = zp[0], z1 = zp[1], z2 = zp[2], z3 = zp[3];
    float zv[16] = {z0.x, z0.y, z0.z, z0.w, z1.x, z1.y, z1.z, z1.w,
                    z2.x, z2.y, z2.z, z2.w, z3.x, z3.y, z3.z, z3.w};
    float mm = 0.0f;
#pragma unroll
    for (int c = 0; c < 16; c++) mm += zv[c];
    mm *= (1.0f / 16.0f);
    float ss2 = 0.0f;
#pragma unroll
    for (int c = 0; c < 16; c++) { float d = zv[c] - mm; ss2 += d * d; }
    float inv = rsqrtf(ss2 * (1.0f / 16.0f) + 1e-5f);
    float bh0 = 0, bh1 = 0, bh2 = 0, bh3 = 0;
#pragma unroll
    for (int c = 0; c < 16; c++) {
        float zn = (zv[c] - mm) * inv * gzs[c];
        bh0 += zn * wzs[c * 4 + 0];
        bh1 += zn * wzs[c * 4 + 1];
        bh2 += zn * wzs[c * 4 + 2];
        bh3 += zn * wzs[c * 4 + 3];
    }
    size_t bnb = p >> 12;
    size_t pr  = p & 4095;
    __half* dst = biasg + bnb * (4 * 4096) + pr;
    dst[0 * 4096] = __float2half(bh0);
    dst[1 * 4096] = __float2half(bh1);
    dst[2 * 4096] = __float2half(bh2);
    dst[3 * 4096] = __float2half(bh3);
}

// ---------------------------------------------------------------------------
// LayerNorm
// ---------------------------------------------------------------------------
__global__ void ln_kernel(const float* __restrict__ a, const float* __restrict__ s,
                          const float* __restrict__ apbg, const float* __restrict__ ctg,
                          float* __restrict__ a_n, __half* __restrict__ s_apbh,
                          __half* __restrict__ s_cth, __half* __restrict__ s_rh)
{
    int warp = (blockIdx.x * blockDim.x + threadIdx.x) >> 5;
    int lane = threadIdx.x & 31;
    if (warp >= M_) return;
    size_t base = (size_t)warp * CA_;

    float4 av = ((const float4*)(a + base))[lane];
    float sum = av.x + av.y + av.z + av.w;
    float sq  = av.x * av.x + av.y * av.y + av.z * av.z + av.w * av.w;
#pragma unroll
    for (int o = 16; o; o >>= 1) {
        sum += __shfl_xor_sync(0xffffffffu, sum, o);
        sq  += __shfl_xor_sync(0xffffffffu, sq,  o);
    }
    float m   = sum * (1.0f / 128.0f);
    float inv = rsqrtf(sq * (1.0f / 128.0f) - m * m + 1e-5f);
    float4 ao;
    ao.x = (av.x - m) * inv; ao.y = (av.y - m) * inv;
    ao.z = (av.z - m) * inv; ao.w = (av.w - m) * inv;
    ((float4*)(a_n + base))[lane] = ao;

    float4 sv = ((const float4*)(s + base))[lane];
    {
        __half* p = s_rh + base + lane * 4;
        *(__half2*)(p)     = __floats2half2_rn(sv.x, sv.y);
        *(__half2*)(p + 2) = __floats2half2_rn(sv.z, sv.w);
    }

    float sums = sv.x + sv.y + sv.z + sv.w;
    float sqs  = sv.x * sv.x + sv.y * sv.y + sv.z * sv.z + sv.w * sv.w;
#pragma unroll
    for (int o = 16; o; o >>= 1) {
        sums += __shfl_xor_sync(0xffffffffu, sums, o);
        sqs  += __shfl_xor_sync(0xffffffffu, sqs,  o);
    }
    float ms   = sums * (1.0f / 128.0f);
    float invs = rsqrtf(sqs * (1.0f / 128.0f) - ms * ms + 1e-5f);
    float4 sn;
    sn.x = (sv.x - ms) * invs; sn.y = (sv.y - ms) * invs;
    sn.z = (sv.z - ms) * invs; sn.w = (sv.w - ms) * invs;

    float4 g1 = ((const float4*)apbg)[lane];
    float4 g2 = ((const float4*)ctg)[lane];
    {
        __half* p = s_apbh + base + lane * 4;
        *(__half2*)(p)     = __floats2half2_rn(sn.x * g1.x, sn.y * g1.y);
        *(__half2*)(p + 2) = __floats2half2_rn(sn.z * g1.z, sn.w * g1.w);
    }
    {
        __half* p = s_cth + base + lane * 4;
        *(__half2*)(p)     = __floats2half2_rn(sn.x * g2.x, sn.y * g2.y);
        *(__half2*)(p + 2) = __floats2half2_rn(sn.z * g2.z, sn.w * g2.w);
    }
}

// ---------------------------------------------------------------------------
// Multi-segment fp16 GEMM (R10 structure: per-segment CTAs, ldmatrix loads)
// ---------------------------------------------------------------------------
struct Seg {
    const __half* A;
    const __half* Wt;
    const float*  bias;
    void*         C;
    const __half* e1h;
    const float*  e2;
    int           ldC;
    int           ep;     // 0 none, 1 sigmoid, 2 e1h*acc, 3 e1h*acc+e2
    int           outh;   // 1 = write half
};
struct GemmArgs { Seg seg[8]; };

constexpr int HST = 128 * 72;                 // halves per stage
constexpr int GEMM_SMEM = 4 * HST * 2;        // 73728 bytes

__global__ void __launch_bounds__(256, 2) gemm_h(
    int K, int mode, const __half* __restrict__ U1h, const __half* __restrict__ U2h,
    GemmArgs args)
{
    extern __shared__ __half smh[];
    int tid  = threadIdx.x;
    int warp = tid >> 5, lane = tid & 31;
    int wm = (warp >> 2) * 64;
    int wn = (warp & 3) * 32;
    int gid = lane >> 2, qid = lane & 3;
    int row0 = blockIdx.x * 128;
    int y = blockIdx.y;
    const __half* Aseg = args.seg[y].A;
    const __half* Wt   = args.seg[y].Wt;
    int KT = K >> 6;

    uint32_t smBase = smem_u32(smh);
    int lmA = lane & 15, lhA = (lane >> 4) << 3;
    int lmB = lane & 7,  lhB = ((lane >> 3) & 1) << 3;

    auto loadA = [&](int kt, int st) {
        if (mode == 0) {
#pragma unroll
            for (int i = 0; i < 4; i++) {
                int e  = tid + i * 256;
                int r  = e >> 3;
                int c8 = (e & 7) * 8;
                uint32_t dst = smBase + (uint32_t)(st * HST + r * 72 + c8) * 2u;
                cp_async16(dst, Aseg + (size_t)(row0 + r) * K + kt * 64 + c8);
            }
        } else {
            __half* As = smh + st * HST;
#pragma unroll
            for (int i = 0; i < 4; i++) {
                int e  = tid + i * 256;
                int r  = e >> 3;
                int c8 = (e & 7) * 8;
                size_t off = (size_t)(row0 + r) * K + kt * 64 + c8;
                uint4 xu = *(const uint4*)(U1h + off);
                uint4 wu = *(const uint4*)(U2h + off);
                const __half2* xh = (const __half2*)&xu;
                const __half2* wh2 = (const __half2*)&wu;
                __half2 outp[4];
#pragma unroll
                for (int j = 0; j < 4; j++) {
                    float2 xf = __half22float2(xh[j]);
                    float2 wf = __half22float2(wh2[j]);
                    outp[j] = __floats2half2_rn(xf.x * sigmoidf_(xf.x) * wf.x,
                                                xf.y * sigmoidf_(xf.y) * wf.y);
                }
                *(uint4*)(As + r * 72 + c8) = *(uint4*)outp;
            }
        }
    };
    auto loadB = [&](int kt, int st) {
#pragma unroll
        for (int i = 0; i < 4; i++) {
            int e  = tid + i * 256;
            int n  = e >> 3;
            int c8 = (e & 7) * 8;
            uint32_t dst = smBase + (uint32_t)(2 * HST + st * HST + n * 72 + c8) * 2u;
            cp_async16(dst, Wt + (size_t)n * K + kt * 64 + c8);
        }
    };

    float c[4][4][4];
#pragma unroll
    for (int mi = 0; mi < 4; mi++)
#pragma unroll
        for (int ni = 0; ni < 4; ni++)
#pragma unroll
            for (int r = 0; r < 4; r++) c[mi][ni][r] = 0.0f;

    loadA(0, 0); loadB(0, 0); cp_commit();
    if (KT > 1) { loadA(1, 1); loadB(1, 1); cp_commit(); }

    for (int kt = 0; kt < KT; kt++) {
        cp_wait1();
        __syncthreads();
        int st = kt & 1;
        uint32_t asB = smBase + (uint32_t)(st * HST) * 2u;
        uint32_t bsB = smBase + (uint32_t)(2 * HST + st * HST) * 2u;
#pragma unroll
        for (int ks = 0; ks < 4; ks++) {
            int kb = ks * 16;
            uint32_t af[4][4], bf[4][2];
#pragma unroll
            for (int mi = 0; mi < 4; mi++)
                ldsm_x4(af[mi], asB + (uint32_t)((wm + mi * 16 + lmA) * 72 + kb + lhA) * 2u);
#pragma unroll
            for (int ni = 0; ni < 4; ni++)
                ldsm_x2(bf[ni], bsB + (uint32_t)((wn + ni * 8 + lmB) * 72 + kb + lhB) * 2u);
#pragma unroll
            for (int mi = 0; mi < 4; mi++)
#pragma unroll
                for (int ni = 0; ni < 4; ni++)
                    MMA_F16(c[mi][ni], af[mi], bf[ni]);
        }
        __syncthreads();
        if (kt + 2 < KT) { loadA(kt + 2, st); loadB(kt + 2, st); }
        cp_commit();
    }

    const float* bias = args.seg[y].bias;
    void* C = args.seg[y].C;
    const __half* e1h = args.seg[y].e1h;
    const float* e2 = args.seg[y].e2;
    int ldC = args.seg[y].ldC;
    int ep  = args.seg[y].ep;
    int outh = args.seg[y].outh;

#pragma unroll
    for (int mi = 0; mi < 4; mi++) {
#pragma unroll
        for (int ni = 0; ni < 4; ni++) {
            int rA = row0 + wm + mi * 16 + gid;
            int cc = wn + ni * 8 + qid * 2;
            float b0 = bias ? bias[cc]     : 0.0f;
            float b1 = bias ? bias[cc + 1] : 0.0f;
#pragma unroll
            for (int h = 0; h < 2; h++) {
                size_t idx = (size_t)(rA + h * 8) * ldC + cc;
                float v0 = c[mi][ni][h * 2 + 0] + b0;
                float v1 = c[mi][ni][h * 2 + 1] + b1;
                if (ep == 1)      { v0 = sigmoidf_(v0); v1 = sigmoidf_(v1); }
                else if (ep == 2) {
                    __half2 e = *(const __half2*)(e1h + idx);
                    v0 *= __low2float(e); v1 *= __high2float(e);
                } else if (ep == 3) {
                    __half2 e = *(const __half2*)(e1h + idx);
                    v0 = __low2float(e)  * v0 + e2[idx];
                    v1 = __high2float(e) * v1 + e2[idx + 1];
                }
                if (outh) *(__half2*)((__half*)C + idx) = __floats2half2_rn(v0, v1);
                else      *(float2*)((float*)C + idx)   = make_float2(v0, v1);
            }
        }
    }
}

// ---------------------------------------------------------------------------
// Combine: a1h = h(gapb*a_n + kapb); a3h = h(gct*a_n + kct)
// ---------------------------------------------------------------------------
__global__ void combine1_kernel(
    const __half* __restrict__ gapbh, const __half* __restrict__ kapbh,
    const __half* __restrict__ gcth,  const __half* __restrict__ kcth,
    const float* __restrict__ a_n,
    __half* __restrict__ a1h, __half* __restrict__ a3h)
{
    size_t i = (size_t)blockIdx.x * blockDim.x + threadIdx.x;
    float4 van = ((const float4*)a_n)[i];

    {
        __half2 g0 = ((const __half2*)gapbh)[2 * i], g1 = ((const __half2*)gapbh)[2 * i + 1];
        __half2 k0 = ((const __half2*)kapbh)[2 * i], k1 = ((const __half2*)kapbh)[2 * i + 1];
        float2 gf0 = __half22float2(g0), gf1 = __half22float2(g1);
        float2 kf0 = __half22float2(k0), kf1 = __half22float2(k1);
        ((__half2*)a1h)[2 * i]     = __floats2half2_rn(gf0.x * van.x + kf0.x, gf0.y * van.y + kf0.y);
        ((__half2*)a1h)[2 * i + 1] = __floats2half2_rn(gf1.x * van.z + kf1.x, gf1.y * van.w + kf1.y);
    }
    {
        __half2 g0 = ((const __half2*)gcth)[2 * i], g1 = ((const __half2*)gcth)[2 * i + 1];
        __half2 k0 = ((const __half2*)kcth)[2 * i], k1 = ((const __half2*)kcth)[2 * i + 1];
        float2 gf0 = __half22float2(g0), gf1 = __half22float2(g1);
        float2 kf0 = __half22float2(k0), kf1 = __half22float2(k1);
        ((__half2*)a3h)[2 * i]     = __floats2half2_rn(gf0.x * van.x + kf0.x, gf0.y * van.y + kf0.y);
        ((__half2*)a3h)[2 * i + 1] = __floats2half2_rn(gf1.x * van.z + kf1.x, gf1.y * van.w + kf1.y);
    }
}

// ---------------------------------------------------------------------------
// Tensor-core local attention, bias from gmem (half). 2 CTA/SM.
// smem: scp fp32 [32][132], Qs/Ks/Vs/Ps half (stride 136) = 103,936 B.
// ---------------------------------------------------------------------------
constexpr int ATTN_SMEM_BYTES = 4224 * 4 + (4352 + 17408 + 17408 + 4352) * 2;

__global__ void __launch_bounds__(256, 2) attn_kernel(
    const __half* __restrict__ qh, const __half* __restrict__ kh,
    const __half* __restrict__ vh, const __half* __restrict__ biasg,
    const __half* __restrict__ gh, __half* __restrict__ obh)
{
    extern __shared__ float sm[];
    float* scp = sm;                       // 4224 fp32
    __half* Qs = (__half*)(sm + 4224);     // 32*136
    __half* Ks = Qs + 4352;                // 128*136
    __half* Vs = Ks + 17408;               // 128*136
    __half* Ps = Vs + 17408;               // 32*136

    int tid = threadIdx.x;
    int warp = tid >> 5, lane = tid & 31;
    int gid = lane >> 2, qid = lane & 3;
    int nb = blockIdx.x, b = blockIdx.y;

    int kbase = nb * 32 - 48;
    int lmA = lane & 15, lhA = (lane >> 4) << 3;
    int lmB = lane & 7,  lhB = ((lane >> 3) & 1) << 3;

    for (int e = tid; e < 512; e += 256) {
        int qq = e >> 4, c8 = (e & 15) * 8;
        *(float4*)(Qs + qq * 136 + c8) =
            *(const float4*)(qh + ((size_t)b * N_ + nb * 32 + qq) * 128 + c8);
    }
    for (int e = tid; e < 2048; e += 256) {
        int j = e >> 4, c8 = (e & 15) * 8;
        int t = kbase + j;
        t = t < 0 ? 0 : (t >= N_ ? N_ - 1 : t);
        size_t off = ((size_t)b * N_ + t) * 128 + c8;
        *(float4*)(Ks + j * 136 + c8) = *(const float4*)(kh + off);
        *(float4*)(Vs + j * 136 + c8) = *(const float4*)(vh + off);
    }
    __syncthreads();

    uint32_t qsBase = smem_u32(Qs);
    uint32_t ksBase = smem_u32(Ks);
    uint32_t vsBase = smem_u32(Vs);
    uint32_t psBase = smem_u32(Ps);
    const float SCALE = 0.17677669529663687f;
    const __half* bgBase = biasg + (size_t)(b * NB_ + nb) * (4 * 4096);

    for (int h = 0; h < H_; h++) {
        // ---- scores: S = Q_h @ K_h^T + bias ----
        {
            int m0 = (warp >> 2) * 16;
            int n0 = (warp & 3) * 32;
            float c[4][4];
#pragma unroll
            for (int nt = 0; nt < 4; nt++)
#pragma unroll
                for (int r = 0; r < 4; r++) c[nt][r] = 0.0f;
#pragma unroll
            for (int ks = 0; ks < 2; ks++) {
                int kb = ks * 16;
                uint32_t af[4];
                ldsm_x4(af, qsBase + (uint32_t)((m0 + lmA) * 136 + h * 32 + kb + lhA) * 2u);
#pragma unroll
                for (int nt = 0; nt < 4; nt++) {
                    uint32_t bf[2];
                    ldsm_x2(bf, ksBase + (uint32_t)((n0 + nt * 8 + lmB) * 136 + h * 32 + kb + lhB) * 2u);
                    MMA_F16(c[nt], af, bf);
                }
            }
            const __half* bg = bgBase + (size_t)h * 4096;
#pragma unroll
            for (int nt = 0; nt < 4; nt++) {
                int col = n0 + nt * 8 + 2 * qid;
                int r0 = m0 + gid, r1 = r0 + 8;
                bool ok0 = (kbase + col >= 0) && (kbase + col < N_);
                bool ok1 = (kbase + col + 1 >= 0) && (kbase + col + 1 < N_);
                float2 bh0 = __half22float2(*(const __half2*)(bg + r0 * 128 + col));
                float2 bh1 = __half22float2(*(const __half2*)(bg + r1 * 128 + col));
                scp[r0 * 132 + col]     = ok0 ? c[nt][0] * SCALE + bh0.x : -1e9f;
                scp[r0 * 132 + col + 1] = ok1 ? c[nt][1] * SCALE + bh0.y : -1e9f;
                scp[r1 * 132 + col]     = ok0 ? c[nt][2] * SCALE + bh1.x : -1e9f;
                scp[r1 * 132 + col + 1] = ok1 ? c[nt][3] * SCALE + bh1.y : -1e9f;
            }
        }
        __syncthreads();

        // ---- softmax (fp32), write P as half ----
#pragma unroll
        for (int rr = 0; rr < 4; rr++) {
            int r = warp * 4 + rr;
            const float* row = scp + r * 132;
            float v0 = row[lane], v1 = row[lane + 32], v2 = row[lane + 64], v3 = row[lane + 96];
            float mx = fmaxf(fmaxf(v0, v1), fmaxf(v2, v3));
#pragma unroll
            for (int o2 = 16; o2; o2 >>= 1) mx = fmaxf(mx, __shfl_xor_sync(0xffffffffu, mx, o2));
            v0 = __expf(v0 - mx); v1 = __expf(v1 - mx);
            v2 = __expf(v2 - mx); v3 = __expf(v3 - mx);
            float sumv = v0 + v1 + v2 + v3;
#pragma unroll
            for (int o2 = 16; o2; o2 >>= 1) sumv += __shfl_xor_sync(0xffffffffu, sumv, o2);
            float invs = 1.0f / sumv;
            __half* pr = Ps + r * 136;
            pr[lane]      = __float2half(v0 * invs);
            pr[lane + 32] = __float2half(v1 * invs);
            pr[lane + 64] = __float2half(v2 * invs);
            pr[lane + 96] = __float2half(v3 * invs);
        }
        __syncthreads();

        // ---- PV: O = P @ V_h ----
        {
            int m0 = (warp >> 2) * 16;
            int nd0 = (warp & 3) * 8;
            float o[4] = {0.0f, 0.0f, 0.0f, 0.0f};
#pragma unroll
            for (int kb = 0; kb < 8; kb++) {
                uint32_t af[4];
                ldsm_x4(af, psBase + (uint32_t)((m0 + lmA) * 136 + kb * 16 + lhA) * 2u);
                int l = lane & 15;
                uint32_t addr = vsBase + (uint32_t)((kb * 16 + l) * 136 + h * 32 + nd0) * 2u;
                uint32_t bf[2];
                asm volatile("ldmatrix.sync.aligned.m8n8.x2.trans.shared.b16 {%0,%1}, [%2];"
                             : "=r"(bf[0]), "=r"(bf[1]) : "r"(addr));
                MMA_F16(o, af, bf);
            }
            int r0 = m0 + gid;
            size_t t0 = ((size_t)b * N_ + nb * 32 + r0) * 128 + h * 32 + nd0 + 2 * qid;
            size_t t1 = t0 + (size_t)8 * 128;
            float2 g0 = __half22float2(*(const __half2*)(gh + t0));
            float2 g1 = __half22float2(*(const __half2*)(gh + t1));
            *(__half2*)(obh + t0) = __floats2half2_rn(g0.x * o[0], g0.y * o[1]);
            *(__half2*)(obh + t1) = __floats2half2_rn(g1.x * o[2], g1.y * o[3]);
        }
        __syncthreads();
    }
}

// ---------------------------------------------------------------------------
// Host launch
// ---------------------------------------------------------------------------
extern "C" void kernel_launch(void* const* d_in, const int* in_sizes, int n_in,
                              void* d_out, int out_size)
{
    const float* a       = (const float*)d_in[0];
    const float* s       = (const float*)d_in[1];
    const float* z       = (const float*)d_in[2];
    const float* apb_gam = (const float*)d_in[3];
    const float* apb_Wg  = (const float*)d_in[4];
    const float* apb_bg  = (const float*)d_in[5];
    const float* apb_Wsk = (const float*)d_in[6];
    const float* Wq      = (const float*)d_in[7];
    const float* bq      = (const float*)d_in[8];
    const float* Wk      = (const float*)d_in[9];
    const float* Wv      = (const float*)d_in[10];
    const float* Wgate   = (const float*)d_in[11];
    const float* Wo      = (const float*)d_in[12];
    const float* gamma_z = (const float*)d_in[13];
    const float* Wz      = (const float*)d_in[14];
    const float* Ws_last = (const float*)d_in[15];
    const float* bs_last = (const float*)d_in[16];
    const float* ct_gam  = (const float*)d_in[17];
    const float* ct_Wg   = (const float*)d_in[18];
    const float* ct_bg   = (const float*)d_in[19];
    const float* ct_Wsk  = (const float*)d_in[20];
    const float* Wa1     = (const float*)d_in[21];
    const float* Wa2     = (const float*)d_in[22];
    const float* Wb      = (const float*)d_in[23];
    const float* Ws      = (const float*)d_in[24];
    const float* bsv     = (const float*)d_in[25];
    float* out = (float*)d_out;

    float* S = nullptr;
    cudaGetSymbolAddress((void**)&S, g_scratch);
    float* a_n = S;
    float* ctp = S + SLOT;
    __half* HB = (__half*)(S + 2 * SLOT);
    auto hslot = [&](int k) { return HB + (size_t)k * SLOT; };  // 26 hslots in 13 slots
    __half* u1h    = hslot(0);   // M x 256
    __half* u2h    = hslot(2);   // M x 256
    __half* s_apbh = hslot(4);
    __half* s_cth  = hslot(5);
    __half* s_rh   = hslot(6);
    __half* a1h    = hslot(7);
    __half* a3h    = hslot(8);
    __half* obh    = hslot(9);
    __half* gapbh  = hslot(10);
    __half* kapbh  = hslot(11);
    __half* gcth   = hslot(12);
    __half* kcth   = hslot(13);
    __half* glasth = hslot(14);
    __half* sgh    = hslot(15);
    __half* qh     = hslot(16);
    __half* khb    = hslot(17);
    __half* vhb    = hslot(18);
    __half* ghb    = hslot(19);
    __half* wh     = hslot(20);  // weights (<SLOT halves)
    __half* biasg  = hslot(21);  // B*NB*4*4096 = 16.7M halves (4 hslots: 21-24)

    __half* wWg   = wh + 0;
    __half* wWsk  = wh + 16384;
    __half* wcWg  = wh + 32768;
    __half* wcWsk = wh + 49152;
    __half* wWsl  = wh + 65536;
    __half* wWs   = wh + 81920;
    __half* wWq   = wh + 98304;
    __half* wWk   = wh + 114688;
    __half* wWv   = wh + 131072;
    __half* wWgt  = wh + 147456;
    __half* wWo   = wh + 163840;
    __half* wWa1  = wh + 180224;  // [256][128]
    __half* wWa2  = wh + 212992;
    __half* wWb   = wh + 245760;  // [128][256]

    WtPack wp;
    const float* wsrc[14] = {apb_Wg, apb_Wsk, ct_Wg, ct_Wsk, Ws_last, Ws, Wq, Wk, Wv,
                             Wgate, Wo, Wa1, Wa2, Wb};
    __half* wdst[14] = {wWg, wWsk, wcWg, wcWsk, wWsl, wWs, wWq, wWk, wWv,
                        wWgt, wWo, wWa1, wWa2, wWb};
    int wK[14] = {128,128,128,128,128,128,128,128,128,128,128,128,128,256};
    int wN[14] = {128,128,128,128,128,128,128,128,128,128,128,256,256,128};
    for (int i = 0; i < 14; i++) { wp.src[i] = wsrc[i]; wp.dst[i] = wdst[i];
                                   wp.K[i] = wK[i]; wp.N[i] = wN[i]; }
    cvtw_kernel<<<dim3(16, 14), 256>>>(wp);

    ln_kernel<<<M_ / 8, 256>>>(a, s, apb_gam, ct_gam, a_n, s_apbh, s_cth, s_rh);

    // z-bias (independent of everything above; fills biasg)
    biasz_kernel<<<(int)((size_t)B_ * NB_ * 4096 / 256), 256>>>(z, gamma_z, Wz, biasg);

    cudaFuncSetAttribute(gemm_h, cudaFuncAttributeMaxDynamicSharedMemorySize, GEMM_SMEM);
    cudaFuncSetAttribute(attn_kernel, cudaFuncAttributeMaxDynamicSharedMemorySize,
                         ATTN_SMEM_BYTES);

    auto mkseg = [&](const __half* A, const __half* Wt, const float* bias, void* C,
                     int ep, const __half* e1h, const float* e2, int ldC, int outh) {
        Seg sgm; sgm.A = A; sgm.Wt = Wt; sgm.bias = bias; sgm.C = C;
        sgm.e1h = e1h; sgm.e2 = e2; sgm.ldC = ldC; sgm.ep = ep; sgm.outh = outh;
        return sgm;
    };

    // G1: 6 segments from s-derived activations
    {
        GemmArgs g{};
        g.seg[0] = mkseg(s_apbh, wWg,   apb_bg,  gapbh,  1, nullptr, nullptr, 128, 1);
        g.seg[1] = mkseg(s_apbh, wWsk,  nullptr, kapbh,  0, nullptr, nullptr, 128, 1);
        g.seg[2] = mkseg(s_cth,  wcWg,  ct_bg,   gcth,   1, nullptr, nullptr, 128, 1);
        g.seg[3] = mkseg(s_cth,  wcWsk, nullptr, kcth,   0, nullptr, nullptr, 128, 1);
        g.seg[4] = mkseg(s_rh,   wWsl,  bs_last, glasth, 1, nullptr, nullptr, 128, 1);
        g.seg[5] = mkseg(s_rh,   wWs,   bsv,     sgh,    1, nullptr, nullptr, 128, 1);
        gemm_h<<<dim3(M_ / 128, 6), 256, GEMM_SMEM>>>(128, 0, nullptr, nullptr, g);
    }

    combine1_kernel<<<(int)(SLOT / 4 / 256), 256>>>(gapbh, kapbh, gcth, kcth, a_n, a1h, a3h);

    // G2: qkv/gate from a1h; u1/u2 from a3h
    {
        GemmArgs g{};
        g.seg[0] = mkseg(a1h, wWq,          bq,      qh,        0, nullptr, nullptr, 128, 1);
        g.seg[1] = mkseg(a1h, wWk,          nullptr, khb,       0, nullptr, nullptr, 128, 1);
        g.seg[2] = mkseg(a1h, wWv,          nullptr, vhb,       0, nullptr, nullptr, 128, 1);
        g.seg[3] = mkseg(a1h, wWgt,         nullptr, ghb,       1, nullptr, nullptr, 128, 1);
        g.seg[4] = mkseg(a3h, wWa1,         nullptr, u1h,       0, nullptr, nullptr, 256, 1);
        g.seg[5] = mkseg(a3h, wWa1 + 16384, nullptr, u1h + 128, 0, nullptr, nullptr, 256, 1);
        g.seg[6] = mkseg(a3h, wWa2,         nullptr, u2h,       0, nullptr, nullptr, 256, 1);
        g.seg[7] = mkseg(a3h, wWa2 + 16384, nullptr, u2h + 128, 0, nullptr, nullptr, 256, 1);
        gemm_h<<<dim3(M_ / 128, 8), 256, GEMM_SMEM>>>(128, 0, nullptr, nullptr, g);
    }

    // G3: ct_out = sgh * (silu(u1)*u2 @ Wb), K=256 (fused loader)
    {
        GemmArgs g{};
        g.seg[0] = mkseg(nullptr, wWb, nullptr, ctp, 2, sgh, nullptr, 128, 0);
        gemm_h<<<dim3(M_ / 128, 1), 256, GEMM_SMEM>>>(256, 1, u1h, u2h, g);
    }

    // attention (bias from gmem)
    attn_kernel<<<dim3(NB_, B_), 256, ATTN_SMEM_BYTES>>>(
        qh, khb, vhb, biasg, ghb, obh);

    // G4: out = glasth * (obh @ Wo) + ctp
    {
        GemmArgs g{};
        g.seg[0] = mkseg(obh, wWo, nullptr, out, 3, glasth, ctp, 128, 0);
        gemm_h<<<dim3(M_ / 128, 1), 256, GEMM_SMEM>>>(128, 0, nullptr, nullptr, g);
    }
}